// round 1
// baseline (speedup 1.0000x reference)
#include <cuda_runtime.h>
#include <math.h>

#define NN 16384
#define NB 4096
#define SCAN_T 1024
#define SEG (NB / SCAN_T)   // 4 elements per scan thread

// ---- static device scratch (no allocation allowed) ----
__device__ float  g_exp[NN];
__device__ float  g_sortedTime[NN];
__device__ float  g_sortedExp[NN];
__device__ int    g_count[NB];
__device__ int    g_start[NB];
__device__ int    g_cursor[NB];
__device__ float  g_bucketExp[NB];
__device__ float  g_suffix[NB];     // sum of exp over buckets strictly greater than b
__device__ float  g_eventSum;
__device__ double g_acc;

__device__ __forceinline__ int bucket_of(float t) {
    int b = (int)(t * (float)NB);
    b = b < 0 ? 0 : b;
    b = b >= NB ? NB - 1 : b;
    return b;
}

__global__ void k0_init() {
    int i = blockIdx.x * blockDim.x + threadIdx.x;
    if (i < NB) { g_count[i] = 0; g_cursor[i] = 0; g_bucketExp[i] = 0.f; }
    if (i == 0) { g_eventSum = 0.f; g_acc = 0.0; }
}

__global__ void k1_hist(const float* __restrict__ risk,
                        const float* __restrict__ time,
                        const float* __restrict__ event) {
    int i = blockIdx.x * blockDim.x + threadIdx.x;
    if (i >= NN) return;
    float e = expf(risk[i]);
    g_exp[i] = e;
    int b = bucket_of(time[i]);
    atomicAdd(&g_count[b], 1);
    atomicAdd(&g_bucketExp[b], e);
    atomicAdd(&g_eventSum, event[i]);
}

// One block: exclusive prefix of counts -> g_start, strict suffix of exp sums -> g_suffix
__global__ void k2_scan() {
    __shared__ int   sc[NB];
    __shared__ float se[NB];
    __shared__ int   pc[SCAN_T];
    __shared__ float pe[SCAN_T];
    int t = threadIdx.x;
    for (int i = t; i < NB; i += SCAN_T) { sc[i] = g_count[i]; se[i] = g_bucketExp[i]; }
    __syncthreads();

    int base = t * SEG;
    int   c = 0; float f = 0.f;
    #pragma unroll
    for (int k = 0; k < SEG; k++) { c += sc[base + k]; f += se[base + k]; }
    pc[t] = c; pe[t] = f;
    __syncthreads();

    // Hillis-Steele inclusive scan over the 1024 per-thread totals
    for (int s = 1; s < SCAN_T; s <<= 1) {
        int   cv = pc[t] + (t >= s ? pc[t - s] : 0);
        float fv = pe[t] + (t >= s ? pe[t - s] : 0.f);
        __syncthreads();
        pc[t] = cv; pe[t] = fv;
        __syncthreads();
    }

    float totalExp = pe[SCAN_T - 1];
    int   coff = (t > 0) ? pc[t - 1] : 0;
    float foff = (t > 0) ? pe[t - 1] : 0.f;

    int crun = coff; float frun = foff;
    #pragma unroll
    for (int k = 0; k < SEG; k++) {
        g_start[base + k] = crun;            // exclusive prefix of counts
        crun += sc[base + k];
        frun += se[base + k];                // inclusive prefix of exp (through bucket base+k)
        g_suffix[base + k] = totalExp - frun; // strict suffix: buckets > base+k
    }
}

__global__ void k3_scatter(const float* __restrict__ time) {
    int i = blockIdx.x * blockDim.x + threadIdx.x;
    if (i >= NN) return;
    float t = time[i];
    int b = bucket_of(t);
    int p = g_start[b] + atomicAdd(&g_cursor[b], 1);
    g_sortedTime[p] = t;
    g_sortedExp[p]  = g_exp[i];
}

__global__ void k4_loss(const float* __restrict__ risk,
                        const float* __restrict__ time,
                        const float* __restrict__ event) {
    int i = blockIdx.x * blockDim.x + threadIdx.x;
    float li = 0.f;
    if (i < NN) {
        float ev = event[i];
        if (ev != 0.f) {
            float t = time[i];
            int b = bucket_of(t);
            float s = g_suffix[b];                 // all strictly-later buckets
            int st = g_start[b], en = st + g_count[b];
            for (int p = st; p < en; p++) {        // own bucket, exact >= compare (handles ties, includes self)
                if (g_sortedTime[p] >= t) s += g_sortedExp[p];
            }
            li = ev * (risk[i] - logf(s));
        }
    }
    __shared__ float red[256];
    red[threadIdx.x] = li;
    __syncthreads();
    for (int s = 128; s > 0; s >>= 1) {
        if (threadIdx.x < s) red[threadIdx.x] += red[threadIdx.x + s];
        __syncthreads();
    }
    if (threadIdx.x == 0) atomicAdd(&g_acc, (double)red[0]);
}

__global__ void k5_final(float* __restrict__ out) {
    out[0] = (float)(-g_acc / (double)g_eventSum);
}

extern "C" void kernel_launch(void* const* d_in, const int* in_sizes, int n_in,
                              void* d_out, int out_size) {
    const float* risk  = (const float*)d_in[0];
    const float* time  = (const float*)d_in[1];
    const float* event = (const float*)d_in[2];
    float* out = (float*)d_out;

    k0_init<<<(NB + 255) / 256, 256>>>();
    k1_hist<<<NN / 256, 256>>>(risk, time, event);
    k2_scan<<<1, SCAN_T>>>();
    k3_scatter<<<NN / 256, 256>>>(time);
    k4_loss<<<NN / 256, 256>>>(risk, time, event);
    k5_final<<<1, 1>>>(out);
}

// round 2
// speedup vs baseline: 1.6090x; 1.6090x over previous
#include <cuda_runtime.h>
#include <math.h>

#define NN 16384
#define NB 4096
#define NBLK 64
#define NTHR 256
#define SEG (NB / NTHR)      // 16 buckets per scan thread (block 0 only)

// ---- static device scratch (statically zero-initialized; self-resetting per replay) ----
__device__ float    g_exp[NN];
__device__ float    g_sortedTime[NN];
__device__ float    g_sortedExp[NN];
__device__ int      g_count[NB];      // zeroed by scan phase after consumption
__device__ int      g_start[NB];      // bucket start (exclusive prefix of counts)
__device__ int      g_cursor[NB];     // scan sets = start; after scatter, = bucket end
__device__ float    g_bucketExp[NB];  // zeroed by scan phase after consumption
__device__ float    g_suffix[NB];     // sum of exp over buckets strictly greater than b
__device__ float    g_evt;            // reset by final phase
__device__ double   g_acc;            // reset by final phase
__device__ unsigned g_bar[4];         // generation barriers: never reset, monotonic

__device__ __forceinline__ int bucket_of(float t) {
    int b = (int)(t * (float)NB);
    b = b < 0 ? 0 : b;
    b = b >= NB ? NB - 1 : b;
    return b;
}

// Grid barrier: all NBLK blocks resident (64 << 148 SMs), generation-counting,
// valid across unlimited graph replays without reset.
__device__ __forceinline__ void gridbar(int s) {
    __syncthreads();
    if (threadIdx.x == 0) {
        __threadfence();
        unsigned my = atomicAdd(&g_bar[s], 1u);             // old value
        unsigned target = (my / NBLK + 1u) * NBLK;          // same for whole generation
        while (*((volatile unsigned*)&g_bar[s]) < target) { __nanosleep(32); }
        __threadfence();
    }
    __syncthreads();
}

__global__ void __launch_bounds__(NTHR, 1)
coxph_fused(const float* __restrict__ risk,
            const float* __restrict__ time,
            const float* __restrict__ event,
            float* __restrict__ out) {
    const int gid = blockIdx.x * NTHR + threadIdx.x;   // exactly NN threads
    const int t   = threadIdx.x;

    __shared__ int   sc[NB];
    __shared__ float se[NB];
    __shared__ int   pc[NTHR];
    __shared__ float pe[NTHR];

    // ---------------- Phase 1: histogram ----------------
    {
        float tm = time[gid];
        float e  = expf(risk[gid]);
        g_exp[gid] = e;
        int b = bucket_of(tm);
        atomicAdd(&g_count[b], 1);
        atomicAdd(&g_bucketExp[b], e);
    }
    gridbar(0);

    // ---------------- Phase 2: scan (block 0 only) ----------------
    if (blockIdx.x == 0) {
        // load counts/exp-sums into smem, then zero globals for the next replay
        for (int i = t; i < NB; i += NTHR) {
            sc[i] = g_count[i];
            se[i] = g_bucketExp[i];
            g_count[i] = 0;
            g_bucketExp[i] = 0.f;
        }
        __syncthreads();

        int base = t * SEG;
        int   c = 0; float f = 0.f;
        #pragma unroll
        for (int k = 0; k < SEG; k++) { c += sc[base + k]; f += se[base + k]; }
        pc[t] = c; pe[t] = f;
        __syncthreads();

        // Hillis-Steele inclusive scan over 256 per-thread totals
        for (int s = 1; s < NTHR; s <<= 1) {
            int   cv = pc[t] + (t >= s ? pc[t - s] : 0);
            float fv = pe[t] + (t >= s ? pe[t - s] : 0.f);
            __syncthreads();
            pc[t] = cv; pe[t] = fv;
            __syncthreads();
        }

        float totalExp = pe[NTHR - 1];
        int   crun = (t > 0) ? pc[t - 1] : 0;
        float frun = (t > 0) ? pe[t - 1] : 0.f;
        #pragma unroll
        for (int k = 0; k < SEG; k++) {
            g_start[base + k]  = crun;             // exclusive prefix of counts
            g_cursor[base + k] = crun;             // scatter cursor (becomes bucket end)
            crun += sc[base + k];
            frun += se[base + k];                  // inclusive prefix of exp
            g_suffix[base + k] = totalExp - frun;  // strict suffix: buckets > base+k
        }
    }
    gridbar(1);

    // ---------------- Phase 3: scatter into bucket-sorted order ----------------
    {
        float tm = time[gid];
        int b = bucket_of(tm);
        int p = atomicAdd(&g_cursor[b], 1);
        g_sortedTime[p] = tm;
        g_sortedExp[p]  = g_exp[gid];
    }
    gridbar(2);

    // ---------------- Phase 4: per-element loss + reduction ----------------
    {
        float ev = event[gid];
        float li = 0.f;
        if (ev != 0.f) {
            float tm = time[gid];
            int b = bucket_of(tm);
            float s  = g_suffix[b];                   // all strictly-later buckets
            int st = g_start[b], en = g_cursor[b];    // cursor == bucket end after scatter
            for (int p = st; p < en; p++) {           // own bucket: exact >= (ties + self)
                if (g_sortedTime[p] >= tm) s += g_sortedExp[p];
            }
            li = ev * (risk[gid] - logf(s));
        }
        // block reduction of (loss, event) reusing scan smem
        float* rl = se;           // 256 floats
        float* re = pe;           // 256 floats
        __syncthreads();          // smem reuse safety
        rl[t] = li; re[t] = ev;
        __syncthreads();
        for (int s = NTHR / 2; s > 0; s >>= 1) {
            if (t < s) { rl[t] += rl[t + s]; re[t] += re[t + s]; }
            __syncthreads();
        }
        if (t == 0) {
            atomicAdd(&g_acc, (double)rl[0]);
            atomicAdd(&g_evt, re[0]);
        }
    }
    gridbar(3);

    // ---------------- Phase 5: finalize (block 0, thread 0) ----------------
    if (blockIdx.x == 0 && t == 0) {
        out[0] = (float)(-g_acc / (double)g_evt);
        g_acc = 0.0;      // self-reset for next replay
        g_evt = 0.f;
    }
}

extern "C" void kernel_launch(void* const* d_in, const int* in_sizes, int n_in,
                              void* d_out, int out_size) {
    const float* risk  = (const float*)d_in[0];
    const float* time  = (const float*)d_in[1];
    const float* event = (const float*)d_in[2];
    float* out = (float*)d_out;
    coxph_fused<<<NBLK, NTHR>>>(risk, time, event, out);
}

// round 3
// speedup vs baseline: 2.3907x; 1.4858x over previous
#include <cuda_runtime.h>
#include <math.h>

#define NN   16384
#define NB   2048
#define NBLK 16
#define NTHR 1024
#define SEG  (NB / NTHR)     // 2 buckets per scan thread
#define FULL 0xFFFFFFFFu

// ---- static device scratch (zero-init; self-resetting per replay) ----
__device__ float    g_exp_unused;          // (kept layout simple)
__device__ float2   g_sorted[NN];          // {time, exp} bucket-sorted
__device__ int      g_count[NB];           // zeroed by scan after consumption
__device__ int      g_start[NB];
__device__ int      g_cursor[NB];          // = start after scan; = end after scatter
__device__ float    g_bucketExp[NB];       // zeroed by scan after consumption
__device__ float    g_suffix[NB];          // exp-sum over buckets strictly > b
__device__ float    g_evt;                 // reset by finalizer
__device__ double   g_acc;                 // reset by finalizer
__device__ unsigned g_bar[3];              // generation barriers (monotone)
__device__ unsigned g_ticket;              // finalize ticket (monotone)

__device__ __forceinline__ int bucket_of(float t) {
    int b = (int)(t * (float)NB);
    b = b < 0 ? 0 : b;
    b = b >= NB ? NB - 1 : b;
    return b;
}

// Grid barrier: NBLK resident blocks, generation-counting, replay-safe, hard spin.
__device__ __forceinline__ void gridbar(int s) {
    __syncthreads();
    if (threadIdx.x == 0) {
        __threadfence();
        unsigned my = atomicAdd(&g_bar[s], 1u);
        unsigned target = (my / NBLK + 1u) * NBLK;
        while (*((volatile unsigned*)&g_bar[s]) < target) {}
        __threadfence();
    }
    __syncthreads();
}

__global__ void __launch_bounds__(NTHR, 1)
coxph_fused(const float* __restrict__ risk,
            const float* __restrict__ time,
            const float* __restrict__ event,
            float* __restrict__ out) {
    const int t    = threadIdx.x;
    const int gid  = blockIdx.x * NTHR + t;      // exactly NN threads
    const int lane = t & 31;
    const int warp = t >> 5;

    __shared__ int   wc[32];
    __shared__ float wf[32];
    __shared__ float rl[32];
    __shared__ float re[32];

    // ---------------- Phase 1: per-element prep + histogram ----------------
    const float theta = risk[gid];
    const float tm    = time[gid];
    float ev          = event[gid];
    const float e     = __expf(theta);
    const int   b     = bucket_of(tm);
    atomicAdd(&g_count[b], 1);
    atomicAdd(&g_bucketExp[b], e);
    gridbar(0);

    // ---------------- Phase 2: scan over NB buckets (block 0) ----------------
    if (blockIdx.x == 0) {
        const int base = t * SEG;
        int   c0 = g_count[base],     c1 = g_count[base + 1];
        float f0 = g_bucketExp[base], f1 = g_bucketExp[base + 1];
        g_count[base] = 0;       g_count[base + 1] = 0;       // reset for next replay
        g_bucketExp[base] = 0.f; g_bucketExp[base + 1] = 0.f;

        int   c = c0 + c1;
        float f = f0 + f1;

        // warp-inclusive scan of per-thread totals
        int ci = c; float fi = f;
        #pragma unroll
        for (int s = 1; s < 32; s <<= 1) {
            int   cc = __shfl_up_sync(FULL, ci, s);
            float ff = __shfl_up_sync(FULL, fi, s);
            if (lane >= s) { ci += cc; fi += ff; }
        }
        if (lane == 31) { wc[warp] = ci; wf[warp] = fi; }
        __syncthreads();
        if (warp == 0) {                       // scan the 32 warp totals
            int cw = wc[lane]; float fw = wf[lane];
            #pragma unroll
            for (int s = 1; s < 32; s <<= 1) {
                int   cc = __shfl_up_sync(FULL, cw, s);
                float ff = __shfl_up_sync(FULL, fw, s);
                if (lane >= s) { cw += cc; fw += ff; }
            }
            wc[lane] = cw; wf[lane] = fw;      // inclusive warp-total prefix
        }
        __syncthreads();

        const int   coff = warp ? wc[warp - 1] : 0;
        const float foff = warp ? wf[warp - 1] : 0.f;
        const float totalExp = wf[31];

        int   crun = (ci + coff) - c;          // exclusive count prefix for bucket 'base'
        float frun = (fi + foff) - f;          // exclusive exp prefix
        g_start[base]  = crun;
        g_cursor[base] = crun;
        g_suffix[base] = totalExp - (frun + f0);
        crun += c0;
        g_start[base + 1]  = crun;
        g_cursor[base + 1] = crun;
        g_suffix[base + 1] = totalExp - (frun + f0 + f1);
    }
    gridbar(1);

    // ---------------- Phase 3: scatter into bucket order ----------------
    {
        int p = atomicAdd(&g_cursor[b], 1);
        g_sorted[p] = make_float2(tm, e);
    }
    gridbar(2);

    // ---------------- Phase 4: per-element loss + global reduction ----------------
    float li = 0.f;
    if (ev != 0.f) {
        float s  = g_suffix[b];                // all strictly-later buckets
        int st = g_start[b], en = g_cursor[b]; // cursor == bucket end now
        for (int p = st; p < en; p++) {        // own bucket: exact >= (ties + self)
            float2 v = g_sorted[p];
            if (v.x >= tm) s += v.y;
        }
        li = ev * (theta - __logf(s));
    }
    // warp reduce, then cross-warp reduce
    #pragma unroll
    for (int o = 16; o; o >>= 1) {
        li += __shfl_xor_sync(FULL, li, o);
        ev += __shfl_xor_sync(FULL, ev, o);
    }
    if (lane == 0) { rl[warp] = li; re[warp] = ev; }
    __syncthreads();
    if (warp == 0) {
        li = rl[lane]; ev = re[lane];
        #pragma unroll
        for (int o = 16; o; o >>= 1) {
            li += __shfl_xor_sync(FULL, li, o);
            ev += __shfl_xor_sync(FULL, ev, o);
        }
        if (lane == 0) {
            atomicAdd(&g_acc, (double)li);
            atomicAdd(&g_evt, ev);
            __threadfence();
            unsigned v = atomicAdd(&g_ticket, 1u);
            if ((v % NBLK) == NBLK - 1) {      // last block finalizes
                __threadfence();
                double acc = *((volatile double*)&g_acc);
                float  evt = *((volatile float*)&g_evt);
                out[0] = (float)(-acc / (double)evt);
                g_acc = 0.0;                   // self-reset for next replay
                g_evt = 0.f;
            }
        }
    }
}

extern "C" void kernel_launch(void* const* d_in, const int* in_sizes, int n_in,
                              void* d_out, int out_size) {
    const float* risk  = (const float*)d_in[0];
    const float* time  = (const float*)d_in[1];
    const float* event = (const float*)d_in[2];
    float* out = (float*)d_out;
    coxph_fused<<<NBLK, NTHR>>>(risk, time, event, out);
}

// round 5
// speedup vs baseline: 3.0862x; 1.2909x over previous
#include <cuda_runtime.h>
#include <math.h>

#define NN    16384
#define NB    8192
#define NBLK  32
#define NTHR  512
#define SEG   (NB / NTHR)        // 16 consecutive buckets per thread in the scan
#define FULL  0xFFFFFFFFu
#define PAD(b) ((b) + ((b) >> 4))  // 17-stride padding: conflict-free strided smem access

// ---- static device scratch (zero-init; parity-rotated or self-resetting) ----
__device__ float    g_e[NN];          // exp(theta), written each launch before use
__device__ int      g_nxt[NN];        // linked-list next (idx+1, 0 = end), written each launch
__device__ float    g_bexp[2][NB];    // per-bucket exp sums; parity p used, 1-p reset in-flight
__device__ int      g_head[2][NB];    // bucket list heads (idx+1, 0 = empty); same parity scheme
__device__ float    g_evt;            // reset by finalizer
__device__ double   g_acc;            // reset by finalizer
__device__ unsigned g_bar;            // generation barrier (monotone, replay-safe)
__device__ unsigned g_ticket;         // finalize ticket (monotone)
__device__ unsigned g_gen;            // launch generation (bumped by finalizer)

__device__ __forceinline__ int bucket_of(float t) {
    int b = (int)(t * (float)NB);
    b = b < 0 ? 0 : b;
    b = b >= NB ? NB - 1 : b;
    return b;
}

// Single grid barrier: NBLK resident blocks, generation-counting, hard spin.
__device__ __forceinline__ void gridbar() {
    __syncthreads();
    if (threadIdx.x == 0) {
        __threadfence();
        unsigned my = atomicAdd(&g_bar, 1u);
        unsigned target = (my / NBLK + 1u) * NBLK;
        while (*((volatile unsigned*)&g_bar) < target) {}
        __threadfence();
    }
    __syncthreads();
}

__global__ void __launch_bounds__(NTHR, 1)
coxph_fused(const float* __restrict__ risk,
            const float* __restrict__ time,
            const float* __restrict__ event,
            float* __restrict__ out) {
    const int  t    = threadIdx.x;
    const int  gid  = blockIdx.x * NTHR + t;     // exactly NN threads
    const int  lane = t & 31;
    const int  warp = t >> 5;                    // 16 warps

    __shared__ float ssuf[NB + NB / 16];         // padded strict-suffix table (~34 KB)
    __shared__ float wtot[16];
    __shared__ float rl[16];
    __shared__ float re[16];

    const unsigned gen = *((volatile unsigned*)&g_gen);
    const int p = gen & 1;
    const int q = p ^ 1;

    // ---------------- Phase 1: prep + bucket insert + reset other parity ----------------
    const float theta = risk[gid];
    const float tm    = time[gid];
    float ev          = event[gid];
    const float e     = __expf(theta);
    const int   b     = bucket_of(tm);

    g_e[gid] = e;
    atomicAdd(&g_bexp[p][b], e);
    g_nxt[gid] = atomicExch(&g_head[p][b], gid + 1);   // push-front; 0 = empty

    // reset the parity nobody reads this launch (ready for next launch)
    if (t < NB / NBLK) {                                // 256 threads x 32 blocks = NB
        int r = blockIdx.x * (NB / NBLK) + t;
        g_bexp[q][r] = 0.f;
        g_head[q][r] = 0;
    }
    gridbar();   // the ONLY grid barrier

    // ---------------- Phase 2: redundant per-block suffix scan into smem ----------------
    {
        // each thread owns 16 consecutive buckets; loads are warp-contiguous (2KB/warp)
        float f[SEG];
        const float4* src = (const float4*)&g_bexp[p][t * SEG];
        #pragma unroll
        for (int k = 0; k < 4; k++) {
            float4 v = src[k];
            f[k * 4 + 0] = v.x; f[k * 4 + 1] = v.y;
            f[k * 4 + 2] = v.z; f[k * 4 + 3] = v.w;
        }
        float c = 0.f;
        #pragma unroll
        for (int k = 0; k < SEG; k++) c += f[k];

        // warp-inclusive scan of per-thread totals
        float ci = c;
        #pragma unroll
        for (int s = 1; s < 32; s <<= 1) {
            float cc = __shfl_up_sync(FULL, ci, s);
            if (lane >= s) ci += cc;
        }
        if (lane == 31) wtot[warp] = ci;
        __syncthreads();
        if (warp == 0) {                      // scan 16 warp totals
            float cw = (lane < 16) ? wtot[lane] : 0.f;
            #pragma unroll
            for (int s = 1; s < 16; s <<= 1) {
                float cc = __shfl_up_sync(FULL, cw, s);
                if (lane >= s) cw += cc;
            }
            if (lane < 16) wtot[lane] = cw;   // inclusive warp prefix
        }
        __syncthreads();

        const float total = wtot[15];
        float running = (warp ? wtot[warp - 1] : 0.f) + (ci - c);  // exclusive prefix
        #pragma unroll
        for (int k = 0; k < SEG; k++) {
            running += f[k];                              // inclusive through bucket t*SEG+k
            ssuf[PAD(t * SEG + k)] = total - running;     // strict suffix (buckets > b)
        }
    }
    __syncthreads();

    // ---------------- Phase 3: per-element loss (suffix + exact own-bucket walk) ----------
    float li = 0.f;
    if (ev != 0.f) {
        float s = ssuf[PAD(b)];                           // all strictly-later buckets
        int node = g_head[p][b];                          // own bucket: exact >= (ties + self)
        while (node) {
            int j = node - 1;
            if (time[j] >= tm) s += g_e[j];
            node = g_nxt[j];
        }
        li = ev * (theta - __logf(s));
    }

    // ---------------- Phase 4: reduction + ticket finalize (no barrier) ----------------
    #pragma unroll
    for (int o = 16; o; o >>= 1) {
        li += __shfl_xor_sync(FULL, li, o);
        ev += __shfl_xor_sync(FULL, ev, o);
    }
    if (lane == 0) { rl[warp] = li; re[warp] = ev; }
    __syncthreads();
    if (warp == 0) {
        li = (lane < 16) ? rl[lane] : 0.f;
        ev = (lane < 16) ? re[lane] : 0.f;
        #pragma unroll
        for (int o = 8; o; o >>= 1) {
            li += __shfl_xor_sync(FULL, li, o);
            ev += __shfl_xor_sync(FULL, ev, o);
        }
        if (lane == 0) {
            atomicAdd(&g_acc, (double)li);
            atomicAdd(&g_evt, ev);
            __threadfence();
            unsigned v = atomicAdd(&g_ticket, 1u);
            if ((v % NBLK) == NBLK - 1) {                 // last block finalizes
                __threadfence();
                double acc = *((volatile double*)&g_acc);
                float  evt = *((volatile float*)&g_evt);
                out[0] = (float)(-acc / (double)evt);
                g_acc = 0.0;                              // self-reset for next replay
                g_evt = 0.f;
                g_gen = gen + 1u;                         // flip parity for next launch
            }
        }
    }
}

extern "C" void kernel_launch(void* const* d_in, const int* in_sizes, int n_in,
                              void* d_out, int out_size) {
    const float* risk  = (const float*)d_in[0];
    const float* time  = (const float*)d_in[1];
    const float* event = (const float*)d_in[2];
    float* out = (float*)d_out;
    coxph_fused<<<NBLK, NTHR>>>(risk, time, event, out);
}

// round 6
// speedup vs baseline: 3.1542x; 1.0220x over previous
#include <cuda_runtime.h>
#include <math.h>

#define NN    16384
#define NB    8192
#define NBLK  16
#define NTHR  1024
#define SEG   (NB / NTHR)          // 8 buckets per thread in the scan
#define FULL  0xFFFFFFFFu
#define PAD(b) ((b) + ((b) >> 4))  // conflict-free strided smem writes

// ---- static device scratch (zero-init; parity-rotated or self-resetting) ----
__device__ float4   g_node[NN];       // {time, exp, next(bitcast int, idx+1, 0=end), pad}
__device__ float    g_bexp[2][NB];    // per-bucket exp sums; parity p used, 1-p reset in-flight
__device__ int      g_head[2][NB];    // bucket list heads (idx+1, 0=empty)
__device__ float    g_evt;            // reset by finalizer
__device__ double   g_acc;            // reset by finalizer
__device__ unsigned g_bar;            // barrier counter (monotone; +NBLK per execution)
__device__ unsigned g_ticket;         // finalize ticket (monotone)
__device__ unsigned g_gen;            // execution generation (+1 per execution, by finalizer)

__device__ __forceinline__ int bucket_of(float t) {
    int b = (int)(t * (float)NB);
    b = b < 0 ? 0 : b;
    b = b >= NB ? NB - 1 : b;
    return b;
}

__device__ __forceinline__ void red_release_add(unsigned* p, unsigned v) {
    asm volatile("red.release.gpu.global.add.u32 [%0], %1;" :: "l"(p), "r"(v) : "memory");
}
__device__ __forceinline__ unsigned ld_acquire(const unsigned* p) {
    unsigned v;
    asm volatile("ld.acquire.gpu.global.u32 %0, [%1];" : "=r"(v) : "l"(p) : "memory");
    return v;
}

__global__ void __launch_bounds__(NTHR, 1)
coxph_fused(const float* __restrict__ risk,
            const float* __restrict__ time,
            const float* __restrict__ event,
            float* __restrict__ out) {
    const int t    = threadIdx.x;
    const int gid  = blockIdx.x * NTHR + t;      // exactly NN threads
    const int lane = t & 31;
    const int warp = t >> 5;                     // 32 warps

    __shared__ float ssuf[NB + NB / 16];         // padded strict-suffix table (~34 KB)
    __shared__ float wtot[32];
    __shared__ float rl[32];
    __shared__ float re[32];

    const unsigned gen = *((volatile unsigned*)&g_gen);
    const int p = gen & 1;
    const int q = p ^ 1;

    // ---------------- Phase 1: prep + bucket insert + reset other parity ----------------
    const float theta = risk[gid];
    const float tm    = time[gid];
    float ev          = event[gid];
    const float e     = __expf(theta);
    const int   b     = bucket_of(tm);

    atomicAdd(&g_bexp[p][b], e);
    int prev = atomicExch(&g_head[p][b], gid + 1);         // push-front; 0 = empty
    g_node[gid] = make_float4(tm, e, __int_as_float(prev), 0.f);

    // reset the parity nobody reads this launch (ready for next execution)
    if (t < NB / NBLK) {                                   // 512 threads x 16 blocks = NB
        int r = blockIdx.x * (NB / NBLK) + t;
        g_bexp[q][r] = 0.f;
        g_head[q][r] = 0;
    }

    // ---------------- Grid barrier (acq/rel, no full fences) ----------------
    __syncthreads();
    if (t == 0) {
        red_release_add(&g_bar, 1u);
        const unsigned target = (gen + 1u) * NBLK;         // bar advances NBLK per execution
        while (ld_acquire(&g_bar) < target) {}
    }
    __syncthreads();

    // prefetch own-bucket head (independent of the scan below — overlaps L2 latency)
    int node = __ldcg(&g_head[p][b]);

    // ---------------- Phase 2: redundant per-block suffix scan into smem ----------------
    {
        float f[SEG];
        const float4* src = (const float4*)&g_bexp[p][t * SEG];
        float4 v0 = __ldcg(src);
        float4 v1 = __ldcg(src + 1);
        f[0] = v0.x; f[1] = v0.y; f[2] = v0.z; f[3] = v0.w;
        f[4] = v1.x; f[5] = v1.y; f[6] = v1.z; f[7] = v1.w;

        float c = 0.f;
        #pragma unroll
        for (int k = 0; k < SEG; k++) c += f[k];

        float ci = c;                              // warp-inclusive scan of per-thread totals
        #pragma unroll
        for (int s = 1; s < 32; s <<= 1) {
            float cc = __shfl_up_sync(FULL, ci, s);
            if (lane >= s) ci += cc;
        }
        if (lane == 31) wtot[warp] = ci;
        __syncthreads();
        if (warp == 0) {                           // scan the 32 warp totals
            float cw = wtot[lane];
            #pragma unroll
            for (int s = 1; s < 32; s <<= 1) {
                float cc = __shfl_up_sync(FULL, cw, s);
                if (lane >= s) cw += cc;
            }
            wtot[lane] = cw;
        }
        __syncthreads();

        const float total = wtot[31];
        float running = (warp ? wtot[warp - 1] : 0.f) + (ci - c);  // exclusive prefix
        #pragma unroll
        for (int k = 0; k < SEG; k++) {
            running += f[k];                                 // inclusive through bucket t*SEG+k
            ssuf[PAD(t * SEG + k)] = total - running;        // strict suffix (buckets > b)
        }
    }
    __syncthreads();

    // ---------------- Phase 3: per-element loss (suffix + exact own-bucket walk) ----------
    float li = 0.f;
    if (ev != 0.f) {
        float s = ssuf[PAD(b)];                              // all strictly-later buckets
        while (node) {                                       // own bucket: exact >= (ties+self)
            float4 nd = __ldcg(&g_node[node - 1]);           // one 16B load per hop
            if (nd.x >= tm) s += nd.y;
            node = __float_as_int(nd.z);
        }
        li = ev * (theta - __logf(s));
    }

    // ---------------- Phase 4: reduction + ticket finalize (no barrier) ----------------
    #pragma unroll
    for (int o = 16; o; o >>= 1) {
        li += __shfl_xor_sync(FULL, li, o);
        ev += __shfl_xor_sync(FULL, ev, o);
    }
    if (lane == 0) { rl[warp] = li; re[warp] = ev; }
    __syncthreads();
    if (warp == 0) {
        li = rl[lane]; ev = re[lane];
        #pragma unroll
        for (int o = 16; o; o >>= 1) {
            li += __shfl_xor_sync(FULL, li, o);
            ev += __shfl_xor_sync(FULL, ev, o);
        }
        if (lane == 0) {
            atomicAdd(&g_acc, (double)li);
            atomicAdd(&g_evt, ev);
            __threadfence();
            unsigned v = atomicAdd(&g_ticket, 1u);
            if ((v % NBLK) == NBLK - 1) {                    // last block finalizes
                __threadfence();
                double acc = *((volatile double*)&g_acc);
                float  evt = *((volatile float*)&g_evt);
                out[0] = (float)(-acc / (double)evt);
                g_acc = 0.0;                                 // self-reset for next execution
                g_evt = 0.f;
                g_gen = gen + 1u;                            // flip parity / advance targets
            }
        }
    }
}

extern "C" void kernel_launch(void* const* d_in, const int* in_sizes, int n_in,
                              void* d_out, int out_size) {
    const float* risk  = (const float*)d_in[0];
    const float* time  = (const float*)d_in[1];
    const float* event = (const float*)d_in[2];
    float* out = (float*)d_out;
    coxph_fused<<<NBLK, NTHR>>>(risk, time, event, out);
}